// round 9
// baseline (speedup 1.0000x reference)
#include <cuda_runtime.h>
#include <cuda_bf16.h>
#include <math_constants.h>
#include <cstdint>

#define ROWS_TOTAL 16384
#define DIM 1024
#define CDIM 256
#define NCODES 8192

typedef unsigned long long u64;

__device__ float g_h[ROWS_TOTAL * CDIM];            // normalized projections (fp32, for rescore)
__device__ float g_hcsq[NCODES];                    // 0.5*||c||^2
__device__ __nv_bfloat16 g_hh[ROWS_TOTAL * CDIM];   // h bf16 hi
__device__ __nv_bfloat16 g_hl[ROWS_TOTAL * CDIM];   // h bf16 lo
__device__ __nv_bfloat16 g_cbh[NCODES * CDIM];      // codebook bf16 hi
__device__ __nv_bfloat16 g_cbl[NCODES * CDIM];      // codebook bf16 lo
__device__ int2 g_cand[ROWS_TOTAL];                 // top-2 candidates per row

// ---------------- helpers ----------------
__device__ __forceinline__ float lo2(u64 v) { return __uint_as_float((unsigned)v); }
__device__ __forceinline__ float hi2(u64 v) { return __uint_as_float((unsigned)(v >> 32)); }
__device__ __forceinline__ u64 pack2(float l, float h) {
    return ((u64)__float_as_uint(h) << 32) | (u64)__float_as_uint(l);
}
__device__ __forceinline__ u64 splat2(float v) {
    unsigned u = __float_as_uint(v); return ((u64)u << 32) | (u64)u;
}
__device__ __forceinline__ void fma2(u64& d, u64 a, u64 b) {
    asm("fma.rn.f32x2 %0, %1, %2, %0;" : "+l"(d) : "l"(a), "l"(b));
}
__device__ __forceinline__ void cp16(void* sdst, const void* gsrc) {
    unsigned s = (unsigned)__cvta_generic_to_shared(sdst);
    asm volatile("cp.async.cg.shared.global [%0], [%1], 16;\n" :: "r"(s), "l"(gsrc) : "memory");
}
#define CP_COMMIT() asm volatile("cp.async.commit_group;\n" ::: "memory")
#define CP_WAIT0()  asm volatile("cp.async.wait_group 0;\n" ::: "memory")

__device__ __forceinline__ uint32_t smem_u32(const void* p) {
    uint32_t a;
    asm("{ .reg .u64 t; cvta.to.shared.u64 t, %1; cvt.u32.u64 %0, t; }" : "=r"(a) : "l"(p));
    return a;
}
__device__ __forceinline__ void ldsm_x4(uint32_t* r, uint32_t addr) {
    asm volatile("ldmatrix.sync.aligned.m8n8.x4.shared.b16 {%0,%1,%2,%3}, [%4];"
                 : "=r"(r[0]), "=r"(r[1]), "=r"(r[2]), "=r"(r[3]) : "r"(addr));
}
__device__ __forceinline__ void ldsm_x2(uint32_t* r, uint32_t addr) {
    asm volatile("ldmatrix.sync.aligned.m8n8.x2.shared.b16 {%0,%1}, [%2];"
                 : "=r"(r[0]), "=r"(r[1]) : "r"(addr));
}
__device__ __forceinline__ void mma16816(float* d, const uint32_t* a, const uint32_t* b) {
    asm volatile("mma.sync.aligned.m16n8k16.row.col.f32.bf16.bf16.f32 "
                 "{%0,%1,%2,%3}, {%4,%5,%6,%7}, {%8,%9}, {%0,%1,%2,%3};"
                 : "+f"(d[0]), "+f"(d[1]), "+f"(d[2]), "+f"(d[3])
                 : "r"(a[0]), "r"(a[1]), "r"(a[2]), "r"(a[3]), "r"(b[0]), "r"(b[1]));
}

// smem layout (bytes): A[2 splits][64 rows][528B] | B[2 bufs][2 splits][64][528] | csq[2][64]f
#define PITCH    528
#define ASPLIT   33792
#define B_OFF    67584
#define BBUF     67584
#define BSPLIT   33792
#define CSQ_OFF  202752
#define SM_TOTAL 203264
#define RED_OFF  67584            // reduce overlay (on B buf 0, after main loop)

// ---------------------------------------------------------------------------
// Kernel 1: 0.5*||c||^2
// ---------------------------------------------------------------------------
__global__ void __launch_bounds__(256) csq_kernel(const float* __restrict__ cb) {
    int warp = threadIdx.x >> 5, lane = threadIdx.x & 31;
    int row = blockIdx.x * 8 + warp;
    const float* p = cb + (size_t)row * CDIM;
    float s = 0.f;
#pragma unroll
    for (int j = 0; j < 8; ++j) { float v = p[lane + 32 * j]; s = fmaf(v, v, s); }
#pragma unroll
    for (int o = 16; o; o >>= 1) s += __shfl_xor_sync(0xffffffffu, s, o);
    if (lane == 0) g_hcsq[row] = 0.5f * s;
}

// ---------------------------------------------------------------------------
// Kernel 1b: bf16 hi/lo split of codebook
// ---------------------------------------------------------------------------
__global__ void __launch_bounds__(256) cbsplit_kernel(const float* __restrict__ cb) {
    int i = (blockIdx.x * 256 + threadIdx.x) * 4;
#pragma unroll
    for (int j = 0; j < 4; ++j) {
        float v = cb[i + j];
        __nv_bfloat16 h = __float2bfloat16(v);
        g_cbh[i + j] = h;
        g_cbl[i + j] = __float2bfloat16(v - __bfloat162float(h));
    }
}

// ---------------------------------------------------------------------------
// Kernel 2: h = LayerNorm(x @ W^T) -> g_h (fp32) + g_hh/g_hl (bf16 hi/lo)
// ---------------------------------------------------------------------------
__global__ void __launch_bounds__(256) gemm1_ln_kernel(const float* __restrict__ x,
                                                       const float* __restrict__ W) {
    __shared__ float As[32 * 65];
    __shared__ float Bs[32 * 258];
    int tid = threadIdx.x;
    int row0 = blockIdx.x * 64;
    int tx = tid & 31, wy = tid >> 5;

    u64 acc[8][4];
#pragma unroll
    for (int ii = 0; ii < 8; ++ii)
#pragma unroll
        for (int jj = 0; jj < 4; ++jj) acc[ii][jj] = 0ull;

    for (int k0 = 0; k0 < DIM; k0 += 32) {
#pragma unroll
        for (int p = 0; p < 2; ++p) {
            int i = tid + p * 256;
            int r = i & 63, k4 = i >> 6;
            float4 v = *(const float4*)(x + (size_t)(row0 + r) * DIM + k0 + k4 * 4);
            As[(k4 * 4 + 0) * 65 + r] = v.x; As[(k4 * 4 + 1) * 65 + r] = v.y;
            As[(k4 * 4 + 2) * 65 + r] = v.z; As[(k4 * 4 + 3) * 65 + r] = v.w;
        }
        {
            int k4 = tid & 7, cb_ = tid >> 3;
#pragma unroll
            for (int p = 0; p < 8; ++p) {
                int c = cb_ + p * 32;
                float4 v = *(const float4*)(W + (size_t)c * DIM + k0 + k4 * 4);
                Bs[(k4 * 4 + 0) * 258 + c] = v.x; Bs[(k4 * 4 + 1) * 258 + c] = v.y;
                Bs[(k4 * 4 + 2) * 258 + c] = v.z; Bs[(k4 * 4 + 3) * 258 + c] = v.w;
            }
        }
        __syncthreads();
#pragma unroll
        for (int kk = 0; kk < 32; ++kk) {
            u64 a2[8], b2[4];
#pragma unroll
            for (int ii = 0; ii < 8; ++ii) a2[ii] = splat2(As[kk * 65 + wy * 8 + ii]);
#pragma unroll
            for (int jj = 0; jj < 4; ++jj) b2[jj] = *(const u64*)(Bs + kk * 258 + 2 * tx + 64 * jj);
#pragma unroll
            for (int ii = 0; ii < 8; ++ii)
#pragma unroll
                for (int jj = 0; jj < 4; ++jj) fma2(acc[ii][jj], a2[ii], b2[jj]);
        }
        __syncthreads();
    }

#pragma unroll
    for (int ii = 0; ii < 8; ++ii) {
        float s = 0.f, q = 0.f;
#pragma unroll
        for (int jj = 0; jj < 4; ++jj) {
            float lo = lo2(acc[ii][jj]), hi = hi2(acc[ii][jj]);
            s += lo + hi;
            q = fmaf(lo, lo, q); q = fmaf(hi, hi, q);
        }
#pragma unroll
        for (int o = 16; o; o >>= 1) {
            s += __shfl_xor_sync(0xffffffffu, s, o);
            q += __shfl_xor_sync(0xffffffffu, q, o);
        }
        float mean = s * (1.f / CDIM);
        float var  = q * (1.f / CDIM) - mean * mean;
        float rstd = rsqrtf(var + 1e-5f);
        size_t row = row0 + wy * 8 + ii;
#pragma unroll
        for (int jj = 0; jj < 4; ++jj) {
            float lo = (lo2(acc[ii][jj]) - mean) * rstd;
            float hi = (hi2(acc[ii][jj]) - mean) * rstd;
            size_t off = row * CDIM + 2 * tx + 64 * jj;
            *(u64*)(g_h + off) = pack2(lo, hi);
            __nv_bfloat16 h0 = __float2bfloat16(lo);
            __nv_bfloat16 h1 = __float2bfloat16(hi);
            __nv_bfloat16 l0 = __float2bfloat16(lo - __bfloat162float(h0));
            __nv_bfloat16 l1 = __float2bfloat16(hi - __bfloat162float(h1));
            *(uint32_t*)((unsigned short*)g_hh + off) =
                (uint32_t)__bfloat16_as_ushort(h0) | ((uint32_t)__bfloat16_as_ushort(h1) << 16);
            *(uint32_t*)((unsigned short*)g_hl + off) =
                (uint32_t)__bfloat16_as_ushort(l0) | ((uint32_t)__bfloat16_as_ushort(l1) << 16);
        }
    }
}

// ---------------------------------------------------------------------------
// Kernel 3: bf16x3 warp-MMA (m16n8k16) distance GEMM + per-row top-2.
// 512 threads / 16 warps. CTA = 64 rows x all codes (128 tiles of 64 codes,
// double-buffered). Warp (of 16): rows (warp&3)*16 + [0,16),
// codes (warp>>2)*16 + [0,16). Three INDEPENDENT accumulator sets
// (hi*hi, lo*hi, hi*lo), combined per tile. dist = 0.5||c||^2 - dot.
// ---------------------------------------------------------------------------
__global__ void __launch_bounds__(512, 1) mma_argmin_kernel() {
    extern __shared__ __align__(1024) char smem[];
    uint32_t sb = smem_u32(smem);
    float* csq_s = (float*)(smem + CSQ_OFF);
    int tid = threadIdx.x, lane = tid & 31, warp = tid >> 5;
    int row0 = blockIdx.x * 64;

    // preload: A tile (h bf16 hi/lo), B tile 0, csq slot 0
    for (int i = tid; i < 4096; i += 512) {
        int split = i >> 11, idx = i & 2047, r = idx >> 5, j = idx & 31;
        const __nv_bfloat16* src = (split ? g_hl : g_hh) + (size_t)(row0 + r) * CDIM + j * 8;
        cp16(smem + split * ASPLIT + r * PITCH + j * 16, src);
    }
    for (int i = tid; i < 4096; i += 512) {
        int split = i >> 11, idx = i & 2047, r = idx >> 5, j = idx & 31;
        const __nv_bfloat16* src = (split ? g_cbl : g_cbh) + (size_t)r * CDIM + j * 8;
        cp16(smem + B_OFF + split * BSPLIT + r * PITCH + j * 16, src);
    }
    if (tid < 16) cp16((char*)csq_s + tid * 16, g_hcsq + tid * 4);
    CP_COMMIT();

    int mrow0 = (warp & 3) * 16;        // row group within CTA (4 x 16 rows)
    int ncol0 = (warp >> 2) * 16;       // code group within a 64-code tile (4 x 16)
    // ldmatrix lane addresses (A: x4 over 16 rows; B: x2 over 8 codes)
    uint32_t a_addr = sb + (uint32_t)(mrow0 + (lane & 7) + 8 * ((lane >> 3) & 1)) * PITCH
                         + (uint32_t)(lane >> 4) * 16;
    uint32_t b_addr = sb + B_OFF + (uint32_t)(ncol0 + (lane & 7)) * PITCH
                         + (uint32_t)((lane >> 3) & 1) * 16;

    // thread owns 2 rows (s=0,1) within its 16-row group
    float best1[2], best2[2]; int id1[2], id2[2];
#pragma unroll
    for (int s = 0; s < 2; ++s) { best1[s] = CUDART_INF_F; best2[s] = CUDART_INF_F; id1[s] = 0; id2[s] = 0; }

    for (int t = 0; t < 128; ++t) {
        CP_WAIT0();
        __syncthreads();                           // B[t&1] + csq[t&1] resident; buf (t+1)&1 free

        if (t + 1 < 128) {
            int c0 = (t + 1) * 64;
            char* buf = smem + B_OFF + ((t + 1) & 1) * BBUF;
            for (int i = tid; i < 4096; i += 512) {
                int split = i >> 11, idx = i & 2047, r = idx >> 5, j = idx & 31;
                const __nv_bfloat16* src = (split ? g_cbl : g_cbh) + (size_t)(c0 + r) * CDIM + j * 8;
                cp16(buf + split * BSPLIT + r * PITCH + j * 16, src);
            }
            if (tid < 16) cp16((char*)csq_s + ((t + 1) & 1) * 256 + tid * 16, g_hcsq + c0 + tid * 4);
            CP_COMMIT();
        }

        // 3 independent accumulator sets x 2 nt x 4 regs
        float accH[2][4], accL[2][4], accM[2][4];
#pragma unroll
        for (int nt = 0; nt < 2; ++nt)
#pragma unroll
            for (int r = 0; r < 4; ++r) { accH[nt][r] = 0.f; accL[nt][r] = 0.f; accM[nt][r] = 0.f; }

        uint32_t bb = b_addr + (t & 1) * BBUF;
#pragma unroll 4
        for (int ks = 0; ks < 16; ++ks) {
            uint32_t a[2][4], b[2][2][2];
#pragma unroll
            for (int sp = 0; sp < 2; ++sp)
                ldsm_x4(a[sp], a_addr + sp * ASPLIT + ks * 32);
#pragma unroll
            for (int nt = 0; nt < 2; ++nt)
#pragma unroll
                for (int sp = 0; sp < 2; ++sp)
                    ldsm_x2(b[nt][sp], bb + nt * (8 * PITCH) + sp * BSPLIT + ks * 32);
            // 6 fully independent MMAs
#pragma unroll
            for (int nt = 0; nt < 2; ++nt) mma16816(accH[nt], a[0], b[nt][0]);  // hi*hi
#pragma unroll
            for (int nt = 0; nt < 2; ++nt) mma16816(accL[nt], a[1], b[nt][0]);  // lo*hi
#pragma unroll
            for (int nt = 0; nt < 2; ++nt) mma16816(accM[nt], a[0], b[nt][1]);  // hi*lo
        }

        // top-2 update. D frag: reg r -> row (lane>>2)+8*(r>>1), col (lane&3)*2+(r&1)
        const float* qp = csq_s + (t & 1) * 64;
#pragma unroll
        for (int nt = 0; nt < 2; ++nt) {
            int cin = ncol0 + nt * 8 + (lane & 3) * 2;
#pragma unroll
            for (int r = 0; r < 4; ++r) {
                float dot = accH[nt][r] + accL[nt][r] + accM[nt][r];
                float d = qp[cin + (r & 1)] - dot;
                int code = t * 64 + cin + (r & 1);
                int s = r >> 1;
                if (d < best1[s]) { best2[s] = best1[s]; id2[s] = id1[s]; best1[s] = d; id1[s] = code; }
                else if (d < best2[s]) { best2[s] = d; id2[s] = code; }
            }
        }
    }

    // cross-thread reduce: per row, 4 cg-warps x 4 lanes x top-2 = 32 candidates.
    __syncthreads();
    float* red_d = (float*)(smem + RED_OFF);          // [64][32]
    int*   red_i = (int*)(smem + RED_OFF + 8192);     // [64][32]
#pragma unroll
    for (int s = 0; s < 2; ++s) {
        int row_l = mrow0 + s * 8 + (lane >> 2);
        int e = (warp >> 2) * 8 + (lane & 3) * 2;
        red_d[row_l * 32 + e]     = best1[s];  red_i[row_l * 32 + e]     = id1[s];
        red_d[row_l * 32 + e + 1] = best2[s];  red_i[row_l * 32 + e + 1] = id2[s];
    }
    __syncthreads();
    if (tid < 64) {
        float b1 = CUDART_INF_F, b2 = CUDART_INF_F; int i1 = 0, i2 = 0;
#pragma unroll
        for (int j = 0; j < 32; ++j) {
            float d = red_d[tid * 32 + j]; int ix = red_i[tid * 32 + j];
            if (d < b1 || (d == b1 && ix < i1)) { b2 = b1; i2 = i1; b1 = d; i1 = ix; }
            else if (d < b2 || (d == b2 && ix < i2)) { b2 = d; i2 = ix; }
        }
        g_cand[row0 + tid] = make_int2(i1, i2);
    }
}

// ---------------------------------------------------------------------------
// Kernel 4: exact fp32 rescoring of the top-2 candidates. One warp per row.
// ---------------------------------------------------------------------------
__global__ void __launch_bounds__(256) rescore_kernel(const float* __restrict__ cb,
                                                      float* __restrict__ out) {
    int wid = threadIdx.x >> 5, lane = threadIdx.x & 31;
    int row = blockIdx.x * 8 + wid;
    int2 cand = g_cand[row];
    const float* hr = g_h + (size_t)row * CDIM;
    const float* c1 = cb + (size_t)cand.x * CDIM;
    const float* c2 = cb + (size_t)cand.y * CDIM;
    float d1 = 0.f, d2 = 0.f;
#pragma unroll
    for (int j = 0; j < 8; ++j) {
        float hv = hr[lane + 32 * j];
        d1 = fmaf(hv, c1[lane + 32 * j], d1);
        d2 = fmaf(hv, c2[lane + 32 * j], d2);
    }
#pragma unroll
    for (int o = 16; o; o >>= 1) {
        d1 += __shfl_xor_sync(0xffffffffu, d1, o);
        d2 += __shfl_xor_sync(0xffffffffu, d2, o);
    }
    if (lane == 0) {
        float q1 = g_hcsq[cand.x] - d1;
        float q2 = g_hcsq[cand.y] - d2;
        int bi;
        if (q1 < q2) bi = cand.x;
        else if (q2 < q1) bi = cand.y;
        else bi = min(cand.x, cand.y);
        out[row] = (float)bi;          // float32: harness __output__ dtype
    }
}

// ---------------------------------------------------------------------------
extern "C" void kernel_launch(void* const* d_in, const int* in_sizes, int n_in,
                              void* d_out, int out_size) {
    const float *x = 0, *W = 0, *cbk = 0;
    for (int i = 0; i < n_in; ++i) {
        if      (in_sizes[i] == ROWS_TOTAL * DIM) x   = (const float*)d_in[i];
        else if (in_sizes[i] == CDIM * DIM)       W   = (const float*)d_in[i];
        else if (in_sizes[i] == NCODES * CDIM)    cbk = (const float*)d_in[i];
    }
    float* out = (float*)d_out;
    if (!x || !W || !cbk) return;

    csq_kernel<<<NCODES / 8, 256>>>(cbk);
    cbsplit_kernel<<<NCODES * CDIM / 1024, 256>>>(cbk);
    gemm1_ln_kernel<<<ROWS_TOTAL / 64, 256>>>(x, W);

    cudaFuncSetAttribute(mma_argmin_kernel, cudaFuncAttributeMaxDynamicSharedMemorySize, SM_TOTAL);
    mma_argmin_kernel<<<ROWS_TOTAL / 64, 512, SM_TOTAL>>>();

    rescore_kernel<<<ROWS_TOTAL / 8, 256>>>(cbk, out);
}

// round 10
// speedup vs baseline: 1.0774x; 1.0774x over previous
#include <cuda_runtime.h>
#include <cuda_bf16.h>
#include <math_constants.h>
#include <cstdint>

#define ROWS_TOTAL 16384
#define DIM 1024
#define CDIM 256
#define NCODES 8192

typedef unsigned long long u64;

__device__ float g_h[ROWS_TOTAL * CDIM];            // normalized projections (fp32, for rescore)
__device__ float g_hcsq[NCODES];                    // 0.5*||c||^2
__device__ __nv_bfloat16 g_hh[ROWS_TOTAL * CDIM];   // h bf16 hi
__device__ __nv_bfloat16 g_hl[ROWS_TOTAL * CDIM];   // h bf16 lo
__device__ __nv_bfloat16 g_cbh[NCODES * CDIM];      // codebook bf16 hi
__device__ __nv_bfloat16 g_cbl[NCODES * CDIM];      // codebook bf16 lo
__device__ int2 g_cand[ROWS_TOTAL];                 // top-2 candidates per row

// ---------------- helpers ----------------
__device__ __forceinline__ float lo2(u64 v) { return __uint_as_float((unsigned)v); }
__device__ __forceinline__ float hi2(u64 v) { return __uint_as_float((unsigned)(v >> 32)); }
__device__ __forceinline__ u64 pack2(float l, float h) {
    return ((u64)__float_as_uint(h) << 32) | (u64)__float_as_uint(l);
}
__device__ __forceinline__ u64 splat2(float v) {
    unsigned u = __float_as_uint(v); return ((u64)u << 32) | (u64)u;
}
__device__ __forceinline__ void fma2(u64& d, u64 a, u64 b) {
    asm("fma.rn.f32x2 %0, %1, %2, %0;" : "+l"(d) : "l"(a), "l"(b));
}
__device__ __forceinline__ void cp16(void* sdst, const void* gsrc) {
    unsigned s = (unsigned)__cvta_generic_to_shared(sdst);
    asm volatile("cp.async.cg.shared.global [%0], [%1], 16;\n" :: "r"(s), "l"(gsrc) : "memory");
}
#define CP_COMMIT() asm volatile("cp.async.commit_group;\n" ::: "memory")
#define CP_WAIT0()  asm volatile("cp.async.wait_group 0;\n" ::: "memory")

__device__ __forceinline__ uint32_t smem_u32(const void* p) {
    uint32_t a;
    asm("{ .reg .u64 t; cvta.to.shared.u64 t, %1; cvt.u32.u64 %0, t; }" : "=r"(a) : "l"(p));
    return a;
}
__device__ __forceinline__ void ldsm_x4(uint32_t* r, uint32_t addr) {
    asm volatile("ldmatrix.sync.aligned.m8n8.x4.shared.b16 {%0,%1,%2,%3}, [%4];"
                 : "=r"(r[0]), "=r"(r[1]), "=r"(r[2]), "=r"(r[3]) : "r"(addr));
}
__device__ __forceinline__ void mma16816(float* d, const uint32_t* a, const uint32_t* b) {
    asm volatile("mma.sync.aligned.m16n8k16.row.col.f32.bf16.bf16.f32 "
                 "{%0,%1,%2,%3}, {%4,%5,%6,%7}, {%8,%9}, {%0,%1,%2,%3};"
                 : "+f"(d[0]), "+f"(d[1]), "+f"(d[2]), "+f"(d[3])
                 : "r"(a[0]), "r"(a[1]), "r"(a[2]), "r"(a[3]), "r"(b[0]), "r"(b[1]));
}

// smem layout (bytes):
//   A[2 splits][128 rows][528B]            @ 0       (135,168)
//   B[2 bufs][2 splits][32 codes][528B]    @ 135168  ( 67,584)
//   csq[2 slots][32 floats]                @ 202752  (    256)
#define PITCH    528
#define ASPL     67584
#define B_OFF    135168
#define BSPL     16896
#define BBUF     33792
#define CSQ_OFF  202752
#define SM_TOTAL 203008
#define RED_OFF  135168           // reduce overlay (on B region, after main loop)

// ---------------------------------------------------------------------------
// Kernel 1: 0.5*||c||^2
// ---------------------------------------------------------------------------
__global__ void __launch_bounds__(256) csq_kernel(const float* __restrict__ cb) {
    int warp = threadIdx.x >> 5, lane = threadIdx.x & 31;
    int row = blockIdx.x * 8 + warp;
    const float* p = cb + (size_t)row * CDIM;
    float s = 0.f;
#pragma unroll
    for (int j = 0; j < 8; ++j) { float v = p[lane + 32 * j]; s = fmaf(v, v, s); }
#pragma unroll
    for (int o = 16; o; o >>= 1) s += __shfl_xor_sync(0xffffffffu, s, o);
    if (lane == 0) g_hcsq[row] = 0.5f * s;
}

// ---------------------------------------------------------------------------
// Kernel 1b: bf16 hi/lo split of codebook
// ---------------------------------------------------------------------------
__global__ void __launch_bounds__(256) cbsplit_kernel(const float* __restrict__ cb) {
    int i = (blockIdx.x * 256 + threadIdx.x) * 4;
#pragma unroll
    for (int j = 0; j < 4; ++j) {
        float v = cb[i + j];
        __nv_bfloat16 h = __float2bfloat16(v);
        g_cbh[i + j] = h;
        g_cbl[i + j] = __float2bfloat16(v - __bfloat162float(h));
    }
}

// ---------------------------------------------------------------------------
// Kernel 2: h = LayerNorm(x @ W^T) -> g_h (fp32) + g_hh/g_hl (bf16 hi/lo)
// ---------------------------------------------------------------------------
__global__ void __launch_bounds__(256) gemm1_ln_kernel(const float* __restrict__ x,
                                                       const float* __restrict__ W) {
    __shared__ float As[32 * 65];
    __shared__ float Bs[32 * 258];
    int tid = threadIdx.x;
    int row0 = blockIdx.x * 64;
    int tx = tid & 31, wy = tid >> 5;

    u64 acc[8][4];
#pragma unroll
    for (int ii = 0; ii < 8; ++ii)
#pragma unroll
        for (int jj = 0; jj < 4; ++jj) acc[ii][jj] = 0ull;

    for (int k0 = 0; k0 < DIM; k0 += 32) {
#pragma unroll
        for (int p = 0; p < 2; ++p) {
            int i = tid + p * 256;
            int r = i & 63, k4 = i >> 6;
            float4 v = *(const float4*)(x + (size_t)(row0 + r) * DIM + k0 + k4 * 4);
            As[(k4 * 4 + 0) * 65 + r] = v.x; As[(k4 * 4 + 1) * 65 + r] = v.y;
            As[(k4 * 4 + 2) * 65 + r] = v.z; As[(k4 * 4 + 3) * 65 + r] = v.w;
        }
        {
            int k4 = tid & 7, cb_ = tid >> 3;
#pragma unroll
            for (int p = 0; p < 8; ++p) {
                int c = cb_ + p * 32;
                float4 v = *(const float4*)(W + (size_t)c * DIM + k0 + k4 * 4);
                Bs[(k4 * 4 + 0) * 258 + c] = v.x; Bs[(k4 * 4 + 1) * 258 + c] = v.y;
                Bs[(k4 * 4 + 2) * 258 + c] = v.z; Bs[(k4 * 4 + 3) * 258 + c] = v.w;
            }
        }
        __syncthreads();
#pragma unroll
        for (int kk = 0; kk < 32; ++kk) {
            u64 a2[8], b2[4];
#pragma unroll
            for (int ii = 0; ii < 8; ++ii) a2[ii] = splat2(As[kk * 65 + wy * 8 + ii]);
#pragma unroll
            for (int jj = 0; jj < 4; ++jj) b2[jj] = *(const u64*)(Bs + kk * 258 + 2 * tx + 64 * jj);
#pragma unroll
            for (int ii = 0; ii < 8; ++ii)
#pragma unroll
                for (int jj = 0; jj < 4; ++jj) fma2(acc[ii][jj], a2[ii], b2[jj]);
        }
        __syncthreads();
    }

#pragma unroll
    for (int ii = 0; ii < 8; ++ii) {
        float s = 0.f, q = 0.f;
#pragma unroll
        for (int jj = 0; jj < 4; ++jj) {
            float lo = lo2(acc[ii][jj]), hi = hi2(acc[ii][jj]);
            s += lo + hi;
            q = fmaf(lo, lo, q); q = fmaf(hi, hi, q);
        }
#pragma unroll
        for (int o = 16; o; o >>= 1) {
            s += __shfl_xor_sync(0xffffffffu, s, o);
            q += __shfl_xor_sync(0xffffffffu, q, o);
        }
        float mean = s * (1.f / CDIM);
        float var  = q * (1.f / CDIM) - mean * mean;
        float rstd = rsqrtf(var + 1e-5f);
        size_t row = row0 + wy * 8 + ii;
#pragma unroll
        for (int jj = 0; jj < 4; ++jj) {
            float lo = (lo2(acc[ii][jj]) - mean) * rstd;
            float hi = (hi2(acc[ii][jj]) - mean) * rstd;
            size_t off = row * CDIM + 2 * tx + 64 * jj;
            *(u64*)(g_h + off) = pack2(lo, hi);
            __nv_bfloat16 h0 = __float2bfloat16(lo);
            __nv_bfloat16 h1 = __float2bfloat16(hi);
            __nv_bfloat16 l0 = __float2bfloat16(lo - __bfloat162float(h0));
            __nv_bfloat16 l1 = __float2bfloat16(hi - __bfloat162float(h1));
            *(uint32_t*)((unsigned short*)g_hh + off) =
                (uint32_t)__bfloat16_as_ushort(h0) | ((uint32_t)__bfloat16_as_ushort(h1) << 16);
            *(uint32_t*)((unsigned short*)g_hl + off) =
                (uint32_t)__bfloat16_as_ushort(l0) | ((uint32_t)__bfloat16_as_ushort(l1) << 16);
        }
    }
}

// ---------------------------------------------------------------------------
// Kernel 3 v4: bf16x3 warp-MMA distance GEMM + per-row top-2.
// Grid 128 (single wave), 128 threads / 4 warps. CTA = 128 rows x all codes,
// streamed in 32-code tiles (256 tiles, double-buffered).
// Warp = 32 rows x 32 codes: per k-step 8 ldmatrix.x4 feed 24 MMAs (ratio 3.0).
// Three independent accumulator sets (hi*hi, lo*hi, hi*lo), fp32.
// ---------------------------------------------------------------------------
__global__ void __launch_bounds__(128, 1) mma_argmin_kernel() {
    extern __shared__ __align__(1024) char smem[];
    uint32_t sb = smem_u32(smem);
    float* csq_s = (float*)(smem + CSQ_OFF);
    int tid = threadIdx.x, lane = tid & 31, warp = tid >> 5;
    int row0 = blockIdx.x * 128;

    // preload: A tile (128 rows, bf16 hi/lo), B tile 0 (32 codes), csq slot 0
    for (int i = tid; i < 8192; i += 128) {
        int split = i >> 12, idx = i & 4095, r = idx >> 5, j = idx & 31;
        const __nv_bfloat16* src = (split ? g_hl : g_hh) + (size_t)(row0 + r) * CDIM + j * 8;
        cp16(smem + split * ASPL + r * PITCH + j * 16, src);
    }
    for (int i = tid; i < 2048; i += 128) {
        int split = i >> 10, idx = i & 1023, r = idx >> 5, j = idx & 31;
        const __nv_bfloat16* src = (split ? g_cbl : g_cbh) + (size_t)r * CDIM + j * 8;
        cp16(smem + B_OFF + split * BSPL + r * PITCH + j * 16, src);
    }
    if (tid < 8) cp16((char*)csq_s + tid * 16, g_hcsq + tid * 4);
    CP_COMMIT();

    int mrow0 = warp * 32;   // each warp owns 32 of the 128 rows; all 32 tile-codes
    // A ldmatrix.x4 (m16k16): proven R8 mapping
    uint32_t a_addr = sb + (uint32_t)(mrow0 + (lane & 7) + 8 * ((lane >> 3) & 1)) * PITCH
                         + (uint32_t)(lane >> 4) * 16;
    // B ldmatrix.x4 (n16k16): lanes 0-15 = codes n0-7 (k0-7|k8-15), lanes 16-31 = n8-15
    uint32_t b_addr = sb + B_OFF + (uint32_t)((lane & 7) + 8 * (lane >> 4)) * PITCH
                         + (uint32_t)((lane >> 3) & 1) * 16;

    float best1[4], best2[4]; int id1[4], id2[4];
#pragma unroll
    for (int s = 0; s < 4; ++s) { best1[s] = CUDART_INF_F; best2[s] = CUDART_INF_F; id1[s] = 0; id2[s] = 0; }

    for (int t = 0; t < 256; ++t) {
        CP_WAIT0();
        __syncthreads();                          // B[t&1] + csq[t&1] resident; buf (t+1)&1 free

        if (t + 1 < 256) {
            int c0 = (t + 1) * 32;
            char* buf = smem + B_OFF + ((t + 1) & 1) * BBUF;
            for (int i = tid; i < 2048; i += 128) {
                int split = i >> 10, idx = i & 1023, r = idx >> 5, j = idx & 31;
                const __nv_bfloat16* src = (split ? g_cbl : g_cbh) + (size_t)(c0 + r) * CDIM + j * 8;
                cp16(buf + split * BSPL + r * PITCH + j * 16, src);
            }
            if (tid < 8) cp16((char*)csq_s + ((t + 1) & 1) * 128 + tid * 16, g_hcsq + c0 + tid * 4);
            CP_COMMIT();
        }

        // 3 independent accumulator sets x [mt 2][nt 4][4 regs]
        float accH[2][4][4], accL[2][4][4], accM[2][4][4];
#pragma unroll
        for (int mt = 0; mt < 2; ++mt)
#pragma unroll
            for (int nt = 0; nt < 4; ++nt)
#pragma unroll
                for (int r = 0; r < 4; ++r) { accH[mt][nt][r] = 0.f; accL[mt][nt][r] = 0.f; accM[mt][nt][r] = 0.f; }

        uint32_t bb = b_addr + (t & 1) * BBUF;
#pragma unroll 4
        for (int ks = 0; ks < 16; ++ks) {
            uint32_t a[2][2][4];                  // [mt][split]
#pragma unroll
            for (int mt = 0; mt < 2; ++mt)
#pragma unroll
                for (int sp = 0; sp < 2; ++sp)
                    ldsm_x4(a[mt][sp], a_addr + mt * (16 * PITCH) + sp * ASPL + ks * 32);
            uint32_t b[2][2][4];                  // [split][code-pair]: regs {0,1}=nt even, {2,3}=nt odd
#pragma unroll
            for (int sp = 0; sp < 2; ++sp)
#pragma unroll
                for (int np = 0; np < 2; ++np)
                    ldsm_x4(b[sp][np], bb + np * (16 * PITCH) + sp * BSPL + ks * 32);
            // 24 independent MMAs
#pragma unroll
            for (int mt = 0; mt < 2; ++mt)
#pragma unroll
                for (int nt = 0; nt < 4; ++nt) {
                    const uint32_t* bh = &b[0][nt >> 1][(nt & 1) * 2];
                    const uint32_t* bl = &b[1][nt >> 1][(nt & 1) * 2];
                    mma16816(accH[mt][nt], a[mt][0], bh);   // hi*hi
                    mma16816(accL[mt][nt], a[mt][1], bh);   // lo*hi
                    mma16816(accM[mt][nt], a[mt][0], bl);   // hi*lo
                }
        }

        // top-2 update. D frag: reg r -> row (lane>>2)+8*(r>>1), col (lane&3)*2+(r&1)
        const float* qp = csq_s + (t & 1) * 32;
#pragma unroll
        for (int mt = 0; mt < 2; ++mt)
#pragma unroll
            for (int nt = 0; nt < 4; ++nt) {
                int cin = nt * 8 + (lane & 3) * 2;
#pragma unroll
                for (int r = 0; r < 4; ++r) {
                    float dot = accH[mt][nt][r] + accL[mt][nt][r] + accM[mt][nt][r];
                    float d = qp[cin + (r & 1)] - dot;
                    int code = t * 32 + cin + (r & 1);
                    int s = mt * 2 + (r >> 1);
                    if (d < best1[s]) { best2[s] = best1[s]; id2[s] = id1[s]; best1[s] = d; id1[s] = code; }
                    else if (d < best2[s]) { best2[s] = d; id2[s] = code; }
                }
            }
    }

    // cross-thread reduce: per row, 4 lanes x top-2 = 8 candidates.
    __syncthreads();
    float* red_d = (float*)(smem + RED_OFF);          // [128][8]
    int*   red_i = (int*)(smem + RED_OFF + 4096);     // [128][8]
#pragma unroll
    for (int s = 0; s < 4; ++s) {
        int row_l = mrow0 + (s >> 1) * 16 + (s & 1) * 8 + (lane >> 2);
        int e = (lane & 3) * 2;
        red_d[row_l * 8 + e]     = best1[s];  red_i[row_l * 8 + e]     = id1[s];
        red_d[row_l * 8 + e + 1] = best2[s];  red_i[row_l * 8 + e + 1] = id2[s];
    }
    __syncthreads();
    {
        float b1 = CUDART_INF_F, b2 = CUDART_INF_F; int i1 = 0, i2 = 0;
#pragma unroll
        for (int j = 0; j < 8; ++j) {
            float d = red_d[tid * 8 + j]; int ix = red_i[tid * 8 + j];
            if (d < b1 || (d == b1 && ix < i1)) { b2 = b1; i2 = i1; b1 = d; i1 = ix; }
            else if (d < b2 || (d == b2 && ix < i2)) { b2 = d; i2 = ix; }
        }
        g_cand[row0 + tid] = make_int2(i1, i2);
    }
}

// ---------------------------------------------------------------------------
// Kernel 4: exact fp32 rescoring of the top-2 candidates. One warp per row.
// ---------------------------------------------------------------------------
__global__ void __launch_bounds__(256) rescore_kernel(const float* __restrict__ cb,
                                                      float* __restrict__ out) {
    int wid = threadIdx.x >> 5, lane = threadIdx.x & 31;
    int row = blockIdx.x * 8 + wid;
    int2 cand = g_cand[row];
    const float* hr = g_h + (size_t)row * CDIM;
    const float* c1 = cb + (size_t)cand.x * CDIM;
    const float* c2 = cb + (size_t)cand.y * CDIM;
    float d1 = 0.f, d2 = 0.f;
#pragma unroll
    for (int j = 0; j < 8; ++j) {
        float hv = hr[lane + 32 * j];
        d1 = fmaf(hv, c1[lane + 32 * j], d1);
        d2 = fmaf(hv, c2[lane + 32 * j], d2);
    }
#pragma unroll
    for (int o = 16; o; o >>= 1) {
        d1 += __shfl_xor_sync(0xffffffffu, d1, o);
        d2 += __shfl_xor_sync(0xffffffffu, d2, o);
    }
    if (lane == 0) {
        float q1 = g_hcsq[cand.x] - d1;
        float q2 = g_hcsq[cand.y] - d2;
        int bi;
        if (q1 < q2) bi = cand.x;
        else if (q2 < q1) bi = cand.y;
        else bi = min(cand.x, cand.y);
        out[row] = (float)bi;          // float32: harness __output__ dtype
    }
}

// ---------------------------------------------------------------------------
extern "C" void kernel_launch(void* const* d_in, const int* in_sizes, int n_in,
                              void* d_out, int out_size) {
    const float *x = 0, *W = 0, *cbk = 0;
    for (int i = 0; i < n_in; ++i) {
        if      (in_sizes[i] == ROWS_TOTAL * DIM) x   = (const float*)d_in[i];
        else if (in_sizes[i] == CDIM * DIM)       W   = (const float*)d_in[i];
        else if (in_sizes[i] == NCODES * CDIM)    cbk = (const float*)d_in[i];
    }
    float* out = (float*)d_out;
    if (!x || !W || !cbk) return;

    csq_kernel<<<NCODES / 8, 256>>>(cbk);
    cbsplit_kernel<<<NCODES * CDIM / 1024, 256>>>(cbk);
    gemm1_ln_kernel<<<ROWS_TOTAL / 64, 256>>>(x, W);

    cudaFuncSetAttribute(mma_argmin_kernel, cudaFuncAttributeMaxDynamicSharedMemorySize, SM_TOTAL);
    mma_argmin_kernel<<<ROWS_TOTAL / 128, 128, SM_TOTAL>>>();

    rescore_kernel<<<ROWS_TOTAL / 8, 256>>>(cbk, out);
}

// round 11
// speedup vs baseline: 1.9748x; 1.8329x over previous
#include <cuda_runtime.h>
#include <cuda_fp16.h>
#include <math_constants.h>
#include <cstdint>

#define ROWS_TOTAL 16384
#define DIM 1024
#define CDIM 256
#define NCODES 8192

typedef unsigned long long u64;

__device__ float g_h[ROWS_TOTAL * CDIM];            // normalized projections (fp32, rescore)
__device__ float g_hcsq[NCODES];                    // 0.5*||c||^2
__device__ __half g_hf16[ROWS_TOTAL * CDIM];        // h fp16
__device__ __half g_cf16[NCODES * CDIM];            // codebook fp16
__device__ int4 g_cand4[ROWS_TOTAL];                // top-4 candidates per row

// ---------------- helpers ----------------
__device__ __forceinline__ float lo2(u64 v) { return __uint_as_float((unsigned)v); }
__device__ __forceinline__ float hi2(u64 v) { return __uint_as_float((unsigned)(v >> 32)); }
__device__ __forceinline__ u64 pack2(float l, float h) {
    return ((u64)__float_as_uint(h) << 32) | (u64)__float_as_uint(l);
}
__device__ __forceinline__ u64 splat2(float v) {
    unsigned u = __float_as_uint(v); return ((u64)u << 32) | (u64)u;
}
__device__ __forceinline__ void fma2(u64& d, u64 a, u64 b) {
    asm("fma.rn.f32x2 %0, %1, %2, %0;" : "+l"(d) : "l"(a), "l"(b));
}
__device__ __forceinline__ void cp16(void* sdst, const void* gsrc) {
    unsigned s = (unsigned)__cvta_generic_to_shared(sdst);
    asm volatile("cp.async.cg.shared.global [%0], [%1], 16;\n" :: "r"(s), "l"(gsrc) : "memory");
}
#define CP_COMMIT() asm volatile("cp.async.commit_group;\n" ::: "memory")
#define CP_WAIT0()  asm volatile("cp.async.wait_group 0;\n" ::: "memory")

__device__ __forceinline__ uint32_t smem_u32(const void* p) {
    uint32_t a;
    asm("{ .reg .u64 t; cvta.to.shared.u64 t, %1; cvt.u32.u64 %0, t; }" : "=r"(a) : "l"(p));
    return a;
}
__device__ __forceinline__ void ldsm_x4(uint32_t* r, uint32_t addr) {
    asm volatile("ldmatrix.sync.aligned.m8n8.x4.shared.b16 {%0,%1,%2,%3}, [%4];"
                 : "=r"(r[0]), "=r"(r[1]), "=r"(r[2]), "=r"(r[3]) : "r"(addr));
}
__device__ __forceinline__ void mma16816h(float* d, const uint32_t* a, const uint32_t* b) {
    asm volatile("mma.sync.aligned.m16n8k16.row.col.f32.f16.f16.f32 "
                 "{%0,%1,%2,%3}, {%4,%5,%6,%7}, {%8,%9}, {%0,%1,%2,%3};"
                 : "+f"(d[0]), "+f"(d[1]), "+f"(d[2]), "+f"(d[3])
                 : "r"(a[0]), "r"(a[1]), "r"(a[2]), "r"(a[3]), "r"(b[0]), "r"(b[1]));
}

// smem layout (bytes):
//   A[128 rows][528B]              @ 0       ( 67,584)
//   B[2 bufs][128 codes][528B]     @ 67584   (135,168)
//   csq[2 slots][128 floats]       @ 202752  (  1,024)
#define PITCH    528
#define B_OFF    67584
#define BBUF     67584
#define CSQ_OFF  202752
#define SM_TOTAL 203776
#define RED_OFF  67584            // reduce overlay (B region, after main loop): 32KB

// ---------------------------------------------------------------------------
// Kernel 1: 0.5*||c||^2
// ---------------------------------------------------------------------------
__global__ void __launch_bounds__(256) csq_kernel(const float* __restrict__ cb) {
    int warp = threadIdx.x >> 5, lane = threadIdx.x & 31;
    int row = blockIdx.x * 8 + warp;
    const float* p = cb + (size_t)row * CDIM;
    float s = 0.f;
#pragma unroll
    for (int j = 0; j < 8; ++j) { float v = p[lane + 32 * j]; s = fmaf(v, v, s); }
#pragma unroll
    for (int o = 16; o; o >>= 1) s += __shfl_xor_sync(0xffffffffu, s, o);
    if (lane == 0) g_hcsq[row] = 0.5f * s;
}

// ---------------------------------------------------------------------------
// Kernel 1b: fp16 conversion of codebook
// ---------------------------------------------------------------------------
__global__ void __launch_bounds__(256) cbhalf_kernel(const float* __restrict__ cb) {
    int i = (blockIdx.x * 256 + threadIdx.x) * 4;
    float4 v = *(const float4*)(cb + i);
    __half2 a = __floats2half2_rn(v.x, v.y);
    __half2 b = __floats2half2_rn(v.z, v.w);
    *(__half2*)(g_cf16 + i)     = a;
    *(__half2*)(g_cf16 + i + 2) = b;
}

// ---------------------------------------------------------------------------
// Kernel 2: h = LayerNorm(x @ W^T) -> g_h (fp32) + g_hf16 (fp16)
// ---------------------------------------------------------------------------
__global__ void __launch_bounds__(256) gemm1_ln_kernel(const float* __restrict__ x,
                                                       const float* __restrict__ W) {
    __shared__ float As[32 * 65];
    __shared__ float Bs[32 * 258];
    int tid = threadIdx.x;
    int row0 = blockIdx.x * 64;
    int tx = tid & 31, wy = tid >> 5;

    u64 acc[8][4];
#pragma unroll
    for (int ii = 0; ii < 8; ++ii)
#pragma unroll
        for (int jj = 0; jj < 4; ++jj) acc[ii][jj] = 0ull;

    for (int k0 = 0; k0 < DIM; k0 += 32) {
#pragma unroll
        for (int p = 0; p < 2; ++p) {
            int i = tid + p * 256;
            int r = i & 63, k4 = i >> 6;
            float4 v = *(const float4*)(x + (size_t)(row0 + r) * DIM + k0 + k4 * 4);
            As[(k4 * 4 + 0) * 65 + r] = v.x; As[(k4 * 4 + 1) * 65 + r] = v.y;
            As[(k4 * 4 + 2) * 65 + r] = v.z; As[(k4 * 4 + 3) * 65 + r] = v.w;
        }
        {
            int k4 = tid & 7, cb_ = tid >> 3;
#pragma unroll
            for (int p = 0; p < 8; ++p) {
                int c = cb_ + p * 32;
                float4 v = *(const float4*)(W + (size_t)c * DIM + k0 + k4 * 4);
                Bs[(k4 * 4 + 0) * 258 + c] = v.x; Bs[(k4 * 4 + 1) * 258 + c] = v.y;
                Bs[(k4 * 4 + 2) * 258 + c] = v.z; Bs[(k4 * 4 + 3) * 258 + c] = v.w;
            }
        }
        __syncthreads();
#pragma unroll
        for (int kk = 0; kk < 32; ++kk) {
            u64 a2[8], b2[4];
#pragma unroll
            for (int ii = 0; ii < 8; ++ii) a2[ii] = splat2(As[kk * 65 + wy * 8 + ii]);
#pragma unroll
            for (int jj = 0; jj < 4; ++jj) b2[jj] = *(const u64*)(Bs + kk * 258 + 2 * tx + 64 * jj);
#pragma unroll
            for (int ii = 0; ii < 8; ++ii)
#pragma unroll
                for (int jj = 0; jj < 4; ++jj) fma2(acc[ii][jj], a2[ii], b2[jj]);
        }
        __syncthreads();
    }

#pragma unroll
    for (int ii = 0; ii < 8; ++ii) {
        float s = 0.f, q = 0.f;
#pragma unroll
        for (int jj = 0; jj < 4; ++jj) {
            float lo = lo2(acc[ii][jj]), hi = hi2(acc[ii][jj]);
            s += lo + hi;
            q = fmaf(lo, lo, q); q = fmaf(hi, hi, q);
        }
#pragma unroll
        for (int o = 16; o; o >>= 1) {
            s += __shfl_xor_sync(0xffffffffu, s, o);
            q += __shfl_xor_sync(0xffffffffu, q, o);
        }
        float mean = s * (1.f / CDIM);
        float var  = q * (1.f / CDIM) - mean * mean;
        float rstd = rsqrtf(var + 1e-5f);
        size_t row = row0 + wy * 8 + ii;
#pragma unroll
        for (int jj = 0; jj < 4; ++jj) {
            float lo = (lo2(acc[ii][jj]) - mean) * rstd;
            float hi = (hi2(acc[ii][jj]) - mean) * rstd;
            size_t off = row * CDIM + 2 * tx + 64 * jj;
            *(u64*)(g_h + off) = pack2(lo, hi);
            *(__half2*)(g_hf16 + off) = __floats2half2_rn(lo, hi);
        }
    }
}

// ---------------------------------------------------------------------------
// Kernel 3 v5: fp16 single-MMA distance GEMM + per-row top-2 (thread) -> top-4.
// Grid 128 (single wave), 256 threads / 8 warps. CTA = 128 rows x all codes,
// streamed in 64 tiles of 128 codes (double-buffered).
// Warp (wr=warp&1, wc=warp>>1): rows wr*64+[0,64), codes wc*32+[0,32) of tile.
// Per k-step: 6 ldmatrix.x4 feed 16 independent MMAs.
// ---------------------------------------------------------------------------
__global__ void __launch_bounds__(256, 1) mma_argmin_kernel() {
    extern __shared__ __align__(1024) char smem[];
    uint32_t sb = smem_u32(smem);
    float* csq_s = (float*)(smem + CSQ_OFF);
    int tid = threadIdx.x, lane = tid & 31, warp = tid >> 5;
    int row0 = blockIdx.x * 128;

    // preload: A tile (128 rows fp16), B tile 0 (128 codes), csq slot 0
    for (int i = tid; i < 4096; i += 256) {
        int r = i >> 5, j = i & 31;
        cp16(smem + r * PITCH + j * 16, g_hf16 + (size_t)(row0 + r) * CDIM + j * 8);
    }
    for (int i = tid; i < 4096; i += 256) {
        int r = i >> 5, j = i & 31;
        cp16(smem + B_OFF + r * PITCH + j * 16, g_cf16 + (size_t)r * CDIM + j * 8);
    }
    if (tid < 32) cp16((char*)csq_s + tid * 16, g_hcsq + tid * 4);
    CP_COMMIT();

    int mrow0 = (warp & 1) * 64;
    int ncol0 = (warp >> 1) * 32;
    // A ldmatrix.x4 (m16k16): proven mapping
    uint32_t a_addr = sb + (uint32_t)(mrow0 + (lane & 7) + 8 * ((lane >> 3) & 1)) * PITCH
                         + (uint32_t)(lane >> 4) * 16;
    // B ldmatrix.x4 (n16k16): proven R10 mapping
    uint32_t b_addr = sb + B_OFF + (uint32_t)(ncol0 + (lane & 7) + 8 * (lane >> 4)) * PITCH
                         + (uint32_t)((lane >> 3) & 1) * 16;

    float best1[8], best2[8]; int id1[8], id2[8];
#pragma unroll
    for (int s = 0; s < 8; ++s) { best1[s] = CUDART_INF_F; best2[s] = CUDART_INF_F; id1[s] = 0; id2[s] = 0; }

    for (int t = 0; t < 64; ++t) {
        CP_WAIT0();
        __syncthreads();                          // B[t&1] + csq[t&1] resident; buf (t+1)&1 free

        if (t + 1 < 64) {
            int c0 = (t + 1) * 128;
            char* buf = smem + B_OFF + ((t + 1) & 1) * BBUF;
            for (int i = tid; i < 4096; i += 256) {
                int r = i >> 5, j = i & 31;
                cp16(buf + r * PITCH + j * 16, g_cf16 + (size_t)(c0 + r) * CDIM + j * 8);
            }
            if (tid < 32) cp16((char*)csq_s + ((t + 1) & 1) * 512 + tid * 16, g_hcsq + c0 + tid * 4);
            CP_COMMIT();
        }

        float acc[4][4][4];
#pragma unroll
        for (int mt = 0; mt < 4; ++mt)
#pragma unroll
            for (int nt = 0; nt < 4; ++nt)
#pragma unroll
                for (int r = 0; r < 4; ++r) acc[mt][nt][r] = 0.f;

        uint32_t bb = b_addr + (t & 1) * BBUF;
#pragma unroll 4
        for (int ks = 0; ks < 16; ++ks) {
            uint32_t a[4][4], b[2][4];
#pragma unroll
            for (int mt = 0; mt < 4; ++mt)
                ldsm_x4(a[mt], a_addr + mt * (16 * PITCH) + ks * 32);
#pragma unroll
            for (int np = 0; np < 2; ++np)
                ldsm_x4(b[np], bb + np * (16 * PITCH) + ks * 32);
            // 16 independent MMAs
#pragma unroll
            for (int mt = 0; mt < 4; ++mt)
#pragma unroll
                for (int nt = 0; nt < 4; ++nt)
                    mma16816h(acc[mt][nt], a[mt], &b[nt >> 1][(nt & 1) * 2]);
        }

        // top-2 update. D frag: reg r -> row (lane>>2)+8*(r>>1), col (lane&3)*2+(r&1)
        const float* qp = csq_s + (t & 1) * 128;
#pragma unroll
        for (int mt = 0; mt < 4; ++mt)
#pragma unroll
            for (int nt = 0; nt < 4; ++nt) {
                int cin = ncol0 + nt * 8 + (lane & 3) * 2;
#pragma unroll
                for (int r = 0; r < 4; ++r) {
                    float d = qp[cin + (r & 1)] - acc[mt][nt][r];
                    int code = t * 128 + cin + (r & 1);
                    int s = mt * 2 + (r >> 1);
                    if (d < best1[s]) { best2[s] = best1[s]; id2[s] = id1[s]; best1[s] = d; id1[s] = code; }
                    else if (d < best2[s]) { best2[s] = d; id2[s] = code; }
                }
            }
    }

    // cross-thread reduce: per row, 4 lanes x 4 wc-warps x top-2 = 32 candidates.
    __syncthreads();
    float* red_d = (float*)(smem + RED_OFF);          // [128][32]
    int*   red_i = (int*)(smem + RED_OFF + 16384);    // [128][32]
#pragma unroll
    for (int s = 0; s < 8; ++s) {
        int row_l = (warp & 1) * 64 + (s >> 1) * 16 + (s & 1) * 8 + (lane >> 2);
        int e = (warp >> 1) * 8 + (lane & 3) * 2;
        red_d[row_l * 32 + e]     = best1[s];  red_i[row_l * 32 + e]     = id1[s];
        red_d[row_l * 32 + e + 1] = best2[s];  red_i[row_l * 32 + e + 1] = id2[s];
    }
    __syncthreads();
    if (tid < 128) {
        float bd[4] = {CUDART_INF_F, CUDART_INF_F, CUDART_INF_F, CUDART_INF_F};
        int   bi[4] = {0, 0, 0, 0};
        for (int j = 0; j < 32; ++j) {
            float d = red_d[tid * 32 + j]; int ix = red_i[tid * 32 + j];
            for (int k = 0; k < 4; ++k) {
                if (d < bd[k] || (d == bd[k] && ix < bi[k])) {
                    for (int m = 3; m > k; --m) { bd[m] = bd[m - 1]; bi[m] = bi[m - 1]; }
                    bd[k] = d; bi[k] = ix;
                    break;
                }
            }
        }
        g_cand4[row0 + tid] = make_int4(bi[0], bi[1], bi[2], bi[3]);
    }
}

// ---------------------------------------------------------------------------
// Kernel 4: exact fp32 rescoring of the top-4 candidates. One warp per row.
// ---------------------------------------------------------------------------
__global__ void __launch_bounds__(256) rescore_kernel(const float* __restrict__ cb,
                                                      float* __restrict__ out) {
    int wid = threadIdx.x >> 5, lane = threadIdx.x & 31;
    int row = blockIdx.x * 8 + wid;
    int4 cand = g_cand4[row];
    int c[4] = {cand.x, cand.y, cand.z, cand.w};
    const float* hr = g_h + (size_t)row * CDIM;
    float d[4] = {0.f, 0.f, 0.f, 0.f};
#pragma unroll
    for (int j = 0; j < 8; ++j) {
        float hv = hr[lane + 32 * j];
#pragma unroll
        for (int q = 0; q < 4; ++q)
            d[q] = fmaf(hv, cb[(size_t)c[q] * CDIM + lane + 32 * j], d[q]);
    }
#pragma unroll
    for (int o = 16; o; o >>= 1)
#pragma unroll
        for (int q = 0; q < 4; ++q)
            d[q] += __shfl_xor_sync(0xffffffffu, d[q], o);
    if (lane == 0) {
        float bd = CUDART_INF_F; int bi = 0;
#pragma unroll
        for (int q = 0; q < 4; ++q) {
            float dist = g_hcsq[c[q]] - d[q];     // 0.5||c||^2 - h.c (argmin-equivalent)
            if (dist < bd || (dist == bd && c[q] < bi)) { bd = dist; bi = c[q]; }
        }
        out[row] = (float)bi;                     // float32: harness __output__ dtype
    }
}

// ---------------------------------------------------------------------------
extern "C" void kernel_launch(void* const* d_in, const int* in_sizes, int n_in,
                              void* d_out, int out_size) {
    const float *x = 0, *W = 0, *cbk = 0;
    for (int i = 0; i < n_in; ++i) {
        if      (in_sizes[i] == ROWS_TOTAL * DIM) x   = (const float*)d_in[i];
        else if (in_sizes[i] == CDIM * DIM)       W   = (const float*)d_in[i];
        else if (in_sizes[i] == NCODES * CDIM)    cbk = (const float*)d_in[i];
    }
    float* out = (float*)d_out;
    if (!x || !W || !cbk) return;

    csq_kernel<<<NCODES / 8, 256>>>(cbk);
    cbhalf_kernel<<<NCODES * CDIM / 1024, 256>>>(cbk);
    gemm1_ln_kernel<<<ROWS_TOTAL / 64, 256>>>(x, W);

    cudaFuncSetAttribute(mma_argmin_kernel, cudaFuncAttributeMaxDynamicSharedMemorySize, SM_TOTAL);
    mma_argmin_kernel<<<ROWS_TOTAL / 128, 256, SM_TOTAL>>>();

    rescore_kernel<<<ROWS_TOTAL / 8, 256>>>(cbk, out);
}

// round 12
// speedup vs baseline: 2.5116x; 1.2718x over previous
#include <cuda_runtime.h>
#include <cuda_fp16.h>
#include <math_constants.h>
#include <cstdint>

#define ROWS_TOTAL 16384
#define DIM 1024
#define CDIM 256
#define NCODES 8192

typedef unsigned long long u64;

__device__ float g_h[ROWS_TOTAL * CDIM];            // normalized projections (fp32, rescore)
__device__ float g_hcsq[NCODES];                    // 0.5*||c||^2
__device__ __half g_hf16[ROWS_TOTAL * CDIM];        // h fp16 (argmin input)
__device__ __half g_cf16[NCODES * CDIM];            // codebook fp16
__device__ __half g_xh[ROWS_TOTAL * DIM];           // x fp16 hi
__device__ __half g_xl[ROWS_TOTAL * DIM];           // x fp16 lo
__device__ __half g_Wh[CDIM * DIM];                 // W fp16 hi
__device__ __half g_Wl[CDIM * DIM];                 // W fp16 lo
__device__ int4 g_cand4[ROWS_TOTAL];                // top-4 candidates per row

// ---------------- helpers ----------------
__device__ __forceinline__ void cp16(void* sdst, const void* gsrc) {
    unsigned s = (unsigned)__cvta_generic_to_shared(sdst);
    asm volatile("cp.async.cg.shared.global [%0], [%1], 16;\n" :: "r"(s), "l"(gsrc) : "memory");
}
#define CP_COMMIT() asm volatile("cp.async.commit_group;\n" ::: "memory")
#define CP_WAIT0()  asm volatile("cp.async.wait_group 0;\n" ::: "memory")

__device__ __forceinline__ uint32_t smem_u32(const void* p) {
    uint32_t a;
    asm("{ .reg .u64 t; cvta.to.shared.u64 t, %1; cvt.u32.u64 %0, t; }" : "=r"(a) : "l"(p));
    return a;
}
__device__ __forceinline__ void ldsm_x4(uint32_t* r, uint32_t addr) {
    asm volatile("ldmatrix.sync.aligned.m8n8.x4.shared.b16 {%0,%1,%2,%3}, [%4];"
                 : "=r"(r[0]), "=r"(r[1]), "=r"(r[2]), "=r"(r[3]) : "r"(addr));
}
__device__ __forceinline__ void mma16816h(float* d, const uint32_t* a, const uint32_t* b) {
    asm volatile("mma.sync.aligned.m16n8k16.row.col.f32.f16.f16.f32 "
                 "{%0,%1,%2,%3}, {%4,%5,%6,%7}, {%8,%9}, {%0,%1,%2,%3};"
                 : "+f"(d[0]), "+f"(d[1]), "+f"(d[2]), "+f"(d[3])
                 : "r"(a[0]), "r"(a[1]), "r"(a[2]), "r"(a[3]), "r"(b[0]), "r"(b[1]));
}

// ---------------------------------------------------------------------------
// Kernel 1: 0.5*||c||^2
// ---------------------------------------------------------------------------
__global__ void __launch_bounds__(256) csq_kernel(const float* __restrict__ cb) {
    int warp = threadIdx.x >> 5, lane = threadIdx.x & 31;
    int row = blockIdx.x * 8 + warp;
    const float* p = cb + (size_t)row * CDIM;
    float s = 0.f;
#pragma unroll
    for (int j = 0; j < 8; ++j) { float v = p[lane + 32 * j]; s = fmaf(v, v, s); }
#pragma unroll
    for (int o = 16; o; o >>= 1) s += __shfl_xor_sync(0xffffffffu, s, o);
    if (lane == 0) g_hcsq[row] = 0.5f * s;
}

// ---------------------------------------------------------------------------
// Kernel 1b: fp16 conversion of codebook (argmin B operand)
// ---------------------------------------------------------------------------
__global__ void __launch_bounds__(256) cbhalf_kernel(const float* __restrict__ cb) {
    int i = (blockIdx.x * 256 + threadIdx.x) * 4;
    float4 v = *(const float4*)(cb + i);
    *(__half2*)(g_cf16 + i)     = __floats2half2_rn(v.x, v.y);
    *(__half2*)(g_cf16 + i + 2) = __floats2half2_rn(v.z, v.w);
}

// ---------------------------------------------------------------------------
// Kernel 1c/1d: fp16 hi/lo splits of x and W
// ---------------------------------------------------------------------------
__device__ __forceinline__ void split4(const float* src, __half* dh, __half* dl, int i) {
    float4 v = *(const float4*)(src + i);
    __half h0 = __float2half_rn(v.x), h1 = __float2half_rn(v.y);
    __half h2 = __float2half_rn(v.z), h3 = __float2half_rn(v.w);
    *(__half2*)(dh + i)     = __halves2half2(h0, h1);
    *(__half2*)(dh + i + 2) = __halves2half2(h2, h3);
    *(__half2*)(dl + i)     = __floats2half2_rn(v.x - __half2float(h0), v.y - __half2float(h1));
    *(__half2*)(dl + i + 2) = __floats2half2_rn(v.z - __half2float(h2), v.w - __half2float(h3));
}
__global__ void __launch_bounds__(256) xsplit_kernel(const float* __restrict__ x) {
    split4(x, g_xh, g_xl, (blockIdx.x * 256 + threadIdx.x) * 4);
}
__global__ void __launch_bounds__(256) wsplit_kernel(const float* __restrict__ W) {
    split4(W, g_Wh, g_Wl, (blockIdx.x * 256 + threadIdx.x) * 4);
}

// ---------------------------------------------------------------------------
// Kernel 2 v2: h = LayerNorm(x @ W^T) via fp16 3-term tensor MMA.
// Grid 128 (single wave), 512 threads / 16 warps. CTA = 128 rows x 256 cols,
// K=1024 streamed in 16 chunks of 64 (A and B double-buffered).
// Warp (wr=warp&3, wc=warp>>2): rows wr*32+[0,32), cols wc*64+[0,64).
// dot = xh*Wh + xl*Wh + xh*Wl (fp32 acc; xl*Wl ~2^-22, below fp32 noise).
// LN fused: quad-shfl row partials + cross-warp smem combine.
// smem: A[2buf][2sp][128][144B] @0 (73,728) | B[2buf][2sp][256][144B] (147,456)
// ---------------------------------------------------------------------------
#define G1_PITCH 144
#define G1_ASP   18432
#define G1_ABUF  36864
#define G1_BOFF  73728
#define G1_BSP   36864
#define G1_BBUF  73728
#define G1_SM    221184

__global__ void __launch_bounds__(512, 1) gemm1_mma_kernel() {
    extern __shared__ __align__(1024) char smem[];
    uint32_t sb = smem_u32(smem);
    int tid = threadIdx.x, lane = tid & 31, warp = tid >> 5;
    int row0 = blockIdx.x * 128;
    int wr = warp & 3, wc = warp >> 2;

    // ---- prefetch helper (A: 2048 cp16, B: 4096 cp16) ----
    auto prefetch = [&](int kc, int buf) {
        const __half* xs[2] = { g_xh, g_xl };
        for (int i = tid; i < 2048; i += 512) {
            int sp = i >> 10, idx = i & 1023, r = idx >> 3, j = idx & 7;
            cp16(smem + buf * G1_ABUF + sp * G1_ASP + r * G1_PITCH + j * 16,
                 xs[sp] + (size_t)(row0 + r) * DIM + kc * 64 + j * 8);
        }
        const __half* ws[2] = { g_Wh, g_Wl };
        for (int i = tid; i < 4096; i += 512) {
            int sp = i >> 11, idx = i & 2047, c = idx >> 3, j = idx & 7;
            cp16(smem + G1_BOFF + buf * G1_BBUF + sp * G1_BSP + c * G1_PITCH + j * 16,
                 ws[sp] + (size_t)c * DIM + kc * 64 + j * 8);
        }
    };

    prefetch(0, 0);
    CP_COMMIT();

    // ldmatrix base addresses (proven mappings)
    uint32_t a_addr = sb + (uint32_t)(wr * 32 + (lane & 7) + 8 * ((lane >> 3) & 1)) * G1_PITCH
                         + (uint32_t)(lane >> 4) * 16;
    uint32_t b_addr = sb + G1_BOFF + (uint32_t)(wc * 64 + (lane & 7) + 8 * (lane >> 4)) * G1_PITCH
                         + (uint32_t)((lane >> 3) & 1) * 16;

    float acc[2][8][4];
#pragma unroll
    for (int mt = 0; mt < 2; ++mt)
#pragma unroll
        for (int nt = 0; nt < 8; ++nt)
#pragma unroll
            for (int r = 0; r < 4; ++r) acc[mt][nt][r] = 0.f;

    for (int kc = 0; kc < 16; ++kc) {
        CP_WAIT0();
        __syncthreads();
        if (kc + 1 < 16) { prefetch(kc + 1, (kc + 1) & 1); CP_COMMIT(); }

        uint32_t ab = a_addr + (kc & 1) * G1_ABUF;
        uint32_t bb = b_addr + (kc & 1) * G1_BBUF;
#pragma unroll
        for (int ks = 0; ks < 4; ++ks) {
            uint32_t a[2][2][4];
#pragma unroll
            for (int mt = 0; mt < 2; ++mt)
#pragma unroll
                for (int sp = 0; sp < 2; ++sp)
                    ldsm_x4(a[mt][sp], ab + mt * (16 * G1_PITCH) + sp * G1_ASP + ks * 32);
#pragma unroll
            for (int np = 0; np < 4; ++np) {
                uint32_t bh[4], bl[4];
                ldsm_x4(bh, bb + np * (16 * G1_PITCH) + ks * 32);
                ldsm_x4(bl, bb + np * (16 * G1_PITCH) + G1_BSP + ks * 32);
#pragma unroll
                for (int mt = 0; mt < 2; ++mt)
#pragma unroll
                    for (int nn = 0; nn < 2; ++nn) {
                        int nt = np * 2 + nn;
                        mma16816h(acc[mt][nt], a[mt][0], &bh[nn * 2]);   // xh*Wh
                        mma16816h(acc[mt][nt], a[mt][1], &bh[nn * 2]);   // xl*Wh
                        mma16816h(acc[mt][nt], a[mt][0], &bl[nn * 2]);   // xh*Wl
                    }
            }
        }
    }

    // ---- LN epilogue ----
    __syncthreads();                                 // all smem reads done; reuse A region
    float* sS = (float*)smem;                        // [128 rows][4 wc]
    float* sQ = (float*)(smem + 2048);               // [128 rows][4 wc]

#pragma unroll
    for (int mt = 0; mt < 2; ++mt)
#pragma unroll
        for (int rr = 0; rr < 2; ++rr) {
            float s = 0.f, q = 0.f;
#pragma unroll
            for (int nt = 0; nt < 8; ++nt)
#pragma unroll
                for (int e = 0; e < 2; ++e) {
                    float v = acc[mt][nt][rr * 2 + e];
                    s += v; q = fmaf(v, v, q);
                }
            s += __shfl_xor_sync(0xffffffffu, s, 1); s += __shfl_xor_sync(0xffffffffu, s, 2);
            q += __shfl_xor_sync(0xffffffffu, q, 1); q += __shfl_xor_sync(0xffffffffu, q, 2);
            int row_l = wr * 32 + mt * 16 + rr * 8 + (lane >> 2);
            if ((lane & 3) == 0) { sS[row_l * 4 + wc] = s; sQ[row_l * 4 + wc] = q; }
        }
    __syncthreads();

#pragma unroll
    for (int mt = 0; mt < 2; ++mt)
#pragma unroll
        for (int rr = 0; rr < 2; ++rr) {
            int row_l = wr * 32 + mt * 16 + rr * 8 + (lane >> 2);
            float s = sS[row_l * 4] + sS[row_l * 4 + 1] + sS[row_l * 4 + 2] + sS[row_l * 4 + 3];
            float q = sQ[row_l * 4] + sQ[row_l * 4 + 1] + sQ[row_l * 4 + 2] + sQ[row_l * 4 + 3];
            float mean = s * (1.f / CDIM);
            float var  = q * (1.f / CDIM) - mean * mean;
            float rstd = rsqrtf(var + 1e-5f);
            size_t row = (size_t)(row0 + row_l);
#pragma unroll
            for (int nt = 0; nt < 8; ++nt) {
                float v0 = (acc[mt][nt][rr * 2 + 0] - mean) * rstd;
                float v1 = (acc[mt][nt][rr * 2 + 1] - mean) * rstd;
                size_t col = wc * 64 + nt * 8 + (lane & 3) * 2;
                *(float2*)(g_h + row * CDIM + col) = make_float2(v0, v1);
                *(__half2*)(g_hf16 + row * CDIM + col) = __floats2half2_rn(v0, v1);
            }
        }
}

// ---------------------------------------------------------------------------
// Kernel 3: fp16 single-MMA distance GEMM + per-row top-2 (thread) -> top-4.
// (unchanged from R11: grid 128, 256 thr, CTA = 128 rows x all codes)
// ---------------------------------------------------------------------------
#define PITCH    528
#define B_OFF    67584
#define BBUF     67584
#define CSQ_OFF  202752
#define SM_TOTAL 203776
#define RED_OFF  67584

__global__ void __launch_bounds__(256, 1) mma_argmin_kernel() {
    extern __shared__ __align__(1024) char smem[];
    uint32_t sb = smem_u32(smem);
    float* csq_s = (float*)(smem + CSQ_OFF);
    int tid = threadIdx.x, lane = tid & 31, warp = tid >> 5;
    int row0 = blockIdx.x * 128;

    for (int i = tid; i < 4096; i += 256) {
        int r = i >> 5, j = i & 31;
        cp16(smem + r * PITCH + j * 16, g_hf16 + (size_t)(row0 + r) * CDIM + j * 8);
    }
    for (int i = tid; i < 4096; i += 256) {
        int r = i >> 5, j = i & 31;
        cp16(smem + B_OFF + r * PITCH + j * 16, g_cf16 + (size_t)r * CDIM + j * 8);
    }
    if (tid < 32) cp16((char*)csq_s + tid * 16, g_hcsq + tid * 4);
    CP_COMMIT();

    int mrow0 = (warp & 1) * 64;
    int ncol0 = (warp >> 1) * 32;
    uint32_t a_addr = sb + (uint32_t)(mrow0 + (lane & 7) + 8 * ((lane >> 3) & 1)) * PITCH
                         + (uint32_t)(lane >> 4) * 16;
    uint32_t b_addr = sb + B_OFF + (uint32_t)(ncol0 + (lane & 7) + 8 * (lane >> 4)) * PITCH
                         + (uint32_t)((lane >> 3) & 1) * 16;

    float best1[8], best2[8]; int id1[8], id2[8];
#pragma unroll
    for (int s = 0; s < 8; ++s) { best1[s] = CUDART_INF_F; best2[s] = CUDART_INF_F; id1[s] = 0; id2[s] = 0; }

    for (int t = 0; t < 64; ++t) {
        CP_WAIT0();
        __syncthreads();

        if (t + 1 < 64) {
            int c0 = (t + 1) * 128;
            char* buf = smem + B_OFF + ((t + 1) & 1) * BBUF;
            for (int i = tid; i < 4096; i += 256) {
                int r = i >> 5, j = i & 31;
                cp16(buf + r * PITCH + j * 16, g_cf16 + (size_t)(c0 + r) * CDIM + j * 8);
            }
            if (tid < 32) cp16((char*)csq_s + ((t + 1) & 1) * 512 + tid * 16, g_hcsq + c0 + tid * 4);
            CP_COMMIT();
        }

        float acc[4][4][4];
#pragma unroll
        for (int mt = 0; mt < 4; ++mt)
#pragma unroll
            for (int nt = 0; nt < 4; ++nt)
#pragma unroll
                for (int r = 0; r < 4; ++r) acc[mt][nt][r] = 0.f;

        uint32_t bb = b_addr + (t & 1) * BBUF;
#pragma unroll 4
        for (int ks = 0; ks < 16; ++ks) {
            uint32_t a[4][4], b[2][4];
#pragma unroll
            for (int mt = 0; mt < 4; ++mt)
                ldsm_x4(a[mt], a_addr + mt * (16 * PITCH) + ks * 32);
#pragma unroll
            for (int np = 0; np < 2; ++np)
                ldsm_x4(b[np], bb + np * (16 * PITCH) + ks * 32);
#pragma unroll
            for (int mt = 0; mt < 4; ++mt)
#pragma unroll
                for (int nt = 0; nt < 4; ++nt)
                    mma16816h(acc[mt][nt], a[mt], &b[nt >> 1][(nt & 1) * 2]);
        }

        const float* qp = csq_s + (t & 1) * 128;
#pragma unroll
        for (int mt = 0; mt < 4; ++mt)
#pragma unroll
            for (int nt = 0; nt < 4; ++nt) {
                int cin = ncol0 + nt * 8 + (lane & 3) * 2;
#pragma unroll
                for (int r = 0; r < 4; ++r) {
                    float d = qp[cin + (r & 1)] - acc[mt][nt][r];
                    int code = t * 128 + cin + (r & 1);
                    int s = mt * 2 + (r >> 1);
                    if (d < best1[s]) { best2[s] = best1[s]; id2[s] = id1[s]; best1[s] = d; id1[s] = code; }
                    else if (d < best2[s]) { best2[s] = d; id2[s] = code; }
                }
            }
    }

    __syncthreads();
    float* red_d = (float*)(smem + RED_OFF);
    int*   red_i = (int*)(smem + RED_OFF + 16384);
#pragma unroll
    for (int s = 0; s < 8; ++s) {
        int row_l = (warp & 1) * 64 + (s >> 1) * 16 + (s & 1) * 8 + (lane >> 2);
        int e = (warp >> 1) * 8 + (lane & 3) * 2;
        red_d[row_l * 32 + e]     = best1[s];  red_i[row_l * 32 + e]     = id1[s];
        red_d[row_l * 32 + e + 1] = best2[s];  red_i[row_l * 32 + e + 1] = id2[s];
    }
    __syncthreads();
    if (tid < 128) {
        float bd[4] = {CUDART_INF_F, CUDART_INF_F, CUDART_INF_F, CUDART_INF_F};
        int   bi[4] = {0, 0, 0, 0};
        for (int j = 0; j < 32; ++j) {
            float d = red_d[tid * 32 + j]; int ix = red_i[tid * 32 + j];
            for (int k = 0; k < 4; ++k) {
                if (d < bd[k] || (d == bd[k] && ix < bi[k])) {
                    for (int m = 3; m > k; --m) { bd[m] = bd[m - 1]; bi[m] = bi[m - 1]; }
                    bd[k] = d; bi[k] = ix;
                    break;
                }
            }
        }
        g_cand4[row0 + tid] = make_int4(bi[0], bi[1], bi[2], bi[3]);
    }
}

// ---------------------------------------------------------------------------
// Kernel 4: exact fp32 rescoring of the top-4 candidates. One warp per row.
// ---------------------------------------------------------------------------
__global__ void __launch_bounds__(256) rescore_kernel(const float* __restrict__ cb,
                                                      float* __restrict__ out) {
    int wid = threadIdx.x >> 5, lane = threadIdx.x & 31;
    int row = blockIdx.x * 8 + wid;
    int4 cand = g_cand4[row];
    int c[4] = {cand.x, cand.y, cand.z, cand.w};
    const float* hr = g_h + (size_t)row * CDIM;
    float d[4] = {0.f, 0.f, 0.f, 0.f};
#pragma unroll
    for (int j = 0; j < 8; ++j) {
        float hv = hr[lane + 32 * j];
#pragma unroll
        for (int q = 0; q < 4; ++q)
            d[q] = fmaf(hv, cb[(size_t)c[q] * CDIM + lane + 32 * j], d[q]);
    }
#pragma unroll
    for (int o = 16; o; o >>= 1)
#pragma unroll
        for (int q = 0; q < 4; ++q)
            d[q] += __shfl_xor_sync(0xffffffffu, d[q], o);
    if (lane == 0) {
        float bd = CUDART_INF_F; int bi = 0;
#pragma unroll
        for (int q = 0; q < 4; ++q) {
            float dist = g_hcsq[c[q]] - d[q];
            if (dist < bd || (dist == bd && c[q] < bi)) { bd = dist; bi = c[q]; }
        }
        out[row] = (float)bi;                     // float32: harness __output__ dtype
    }
}

// ---------------------------------------------------------------------------
extern "C" void kernel_launch(void* const* d_in, const int* in_sizes, int n_in,
                              void* d_out, int out_size) {
    const float *x = 0, *W = 0, *cbk = 0;
    for (int i = 0; i < n_in; ++i) {
        if      (in_sizes[i] == ROWS_TOTAL * DIM) x   = (const float*)d_in[i];
        else if (in_sizes[i] == CDIM * DIM)       W   = (const float*)d_in[i];
        else if (in_sizes[i] == NCODES * CDIM)    cbk = (const float*)d_in[i];
    }
    float* out = (float*)d_out;
    if (!x || !W || !cbk) return;

    csq_kernel<<<NCODES / 8, 256>>>(cbk);
    cbhalf_kernel<<<NCODES * CDIM / 1024, 256>>>(cbk);
    xsplit_kernel<<<ROWS_TOTAL * DIM / 1024, 256>>>(x);
    wsplit_kernel<<<CDIM * DIM / 1024, 256>>>(W);

    cudaFuncSetAttribute(gemm1_mma_kernel, cudaFuncAttributeMaxDynamicSharedMemorySize, G1_SM);
    gemm1_mma_kernel<<<ROWS_TOTAL / 128, 512, G1_SM>>>();

    cudaFuncSetAttribute(mma_argmin_kernel, cudaFuncAttributeMaxDynamicSharedMemorySize, SM_TOTAL);
    mma_argmin_kernel<<<ROWS_TOTAL / 128, 256, SM_TOTAL>>>();

    rescore_kernel<<<ROWS_TOTAL / 8, 256>>>(cbk, out);
}